// round 6
// baseline (speedup 1.0000x reference)
#include <cuda_runtime.h>
#include <cuda_bf16.h>
#include <math.h>
#include <stdint.h>

#define N_LEVELS   16
#define N_QUAD     8           // levels 0..7: 32B quad entries (lane-pair coalesced)
#define N_DENSE    10          // levels 8..9: 16B zpair dense grid
#define HASH_BITS  19
#define TABLE_SIZE (1u << HASH_BITS)
#define HASH_MASK  (TABLE_SIZE - 1u)
#define PRIME2     2654435761u
#define PRIME3     805459861u

// Quad grid levels 0..7: entry(cx,cy,cz) = 32B = {zpair(cy), zpair(cy+1%res)}
//   zpair = {tab[h(z)], tab[h(z+1%res)]}.  sum res^3 = 1,023,633
#define QUAD_CAP   1100000
__device__ float4 g_quad[2 * QUAD_CAP];                 // ~35 MB

// Zpair dense grid levels 8..9: entry = 16B zpair. sum res^3 = 3,078,684
#define ZP_CAP     3100000
__device__ float4 g_zp[ZP_CAP];                          // ~50 MB

// Z-paired hash tables for pow2-res hashed levels (12: 256, 15: 512)
//   TZ[s] = {tab[s], tab[(s+Dz)&MASK]}
#define MAX_PAIRED 2
__device__ float4 g_ztab[MAX_PAIRED * TABLE_SIZE];       // ~16.8 MB

struct Params {
    int res[N_LEVELS];
    int quad_base[N_QUAD];
    int qprefix[N_QUAD + 1];
    int zp_base[2];
    int zpprefix[3];
    unsigned pair_mask;
    int      pair_slot[N_LEVELS];
    int      slot_level[MAX_PAIRED];
    unsigned slot_dz[MAX_PAIRED];
    int      n_paired;
};

// XLA-GPU lowers f32 divide to div.full.f32 (approx). The hash trunc
// amplifies 1-ulp differences into wrong indices; reproduce the instruction.
__device__ __forceinline__ float div_full(float a, float b) {
    float r;
    asm("div.full.f32 %0, %1, %2;" : "=f"(r) : "f"(a), "f"(b));
    return r;
}

__device__ __forceinline__ unsigned hash_part(int c, float fres, unsigned prime) {
    float cfrac = div_full((float)c, fres);
    float qf = __fmul_rn(__fmul_rn(__fadd_rn(cfrac, 1.0f), 0.5f), 262144.0f);
    unsigned q = (unsigned)qf;           // positive -> trunc == astype(int64)
    return q * prime;                     // uint32 wrap OK: 2^19 | 2^32
}

// ---------------------------------------------------------------------------
// Fill quad grid (levels 0..7): thread per corner. Own gather; z+1 neighbor
// via shfl (cz fastest); boundary lanes re-gather. Writes zpair into half0 of
// (cy) and half1 of (cy-1 wrap).
// ---------------------------------------------------------------------------
__global__ void __launch_bounds__(256)
fill_quad_kernel(const float* __restrict__ tables, Params p, int total)
{
    int tid0 = blockIdx.x * blockDim.x + threadIdx.x;
    bool valid = tid0 < total;
    int tid = valid ? tid0 : (total - 1);

    int level = 0;
#pragma unroll
    for (int i = 0; i < N_QUAD; i++)
        if (tid >= p.qprefix[i + 1]) level = i + 1;

    int r   = tid - p.qprefix[level];
    int res = p.res[level];
    int cz = r % res;
    int t  = r / res;
    int cy = t % res;
    int cx = t / res;

    float fres = (float)res;
    unsigned hx = hash_part(cx, fres, 1u);
    unsigned hy = hash_part(cy, fres, PRIME2);
    unsigned hz = hash_part(cz, fres, PRIME3);

    const float2* tab = reinterpret_cast<const float2*>(tables)
                        + (size_t)level * TABLE_SIZE;
    float2 v = __ldg(tab + ((hx + hy + hz) & HASH_MASK));

    int lane = threadIdx.x & 31;
    float nx = __shfl_down_sync(0xFFFFFFFFu, v.x, 1);
    float ny = __shfl_down_sync(0xFFFFFFFFu, v.y, 1);
    float2 vn;
    if (cz < res - 1 && lane < 31 && valid) {
        vn = make_float2(nx, ny);
    } else {
        int z1 = (cz + 1 == res) ? 0 : cz + 1;
        unsigned hz1 = hash_part(z1, fres, PRIME3);
        vn = __ldg(tab + ((hx + hy + hz1) & HASH_MASK));
    }

    if (valid) {
        float4 pairv = make_float4(v.x, v.y, vn.x, vn.y);
        size_t base = (size_t)2 * p.quad_base[level];
        int idx  = (cx * res + cy) * res + cz;
        int cym  = (cy == 0) ? res - 1 : cy - 1;
        int idxm = (cx * res + cym) * res + cz;
        g_quad[base + 2 * (size_t)idx]      = pairv;  // half0: own y row
        g_quad[base + 2 * (size_t)idxm + 1] = pairv;  // half1 of (cy-1)
    }
}

// ---------------------------------------------------------------------------
// Fill zpair dense grid (levels 8..9): thread per corner, ONE coalesced
// float4 store (cz fastest => contiguous). Neighbor via shfl.
// ---------------------------------------------------------------------------
__global__ void __launch_bounds__(256)
fill_zp_kernel(const float* __restrict__ tables, Params p, int total)
{
    int tid0 = blockIdx.x * blockDim.x + threadIdx.x;
    bool valid = tid0 < total;
    int tid = valid ? tid0 : (total - 1);

    int li = (tid >= p.zpprefix[1]) ? 1 : 0;
    int level = N_QUAD + li;
    int r   = tid - p.zpprefix[li];
    int res = p.res[level];
    int cz = r % res;
    int t  = r / res;
    int cy = t % res;
    int cx = t / res;

    float fres = (float)res;
    unsigned hx = hash_part(cx, fres, 1u);
    unsigned hy = hash_part(cy, fres, PRIME2);
    unsigned hz = hash_part(cz, fres, PRIME3);

    const float2* tab = reinterpret_cast<const float2*>(tables)
                        + (size_t)level * TABLE_SIZE;
    float2 v = __ldg(tab + ((hx + hy + hz) & HASH_MASK));

    int lane = threadIdx.x & 31;
    float nx = __shfl_down_sync(0xFFFFFFFFu, v.x, 1);
    float ny = __shfl_down_sync(0xFFFFFFFFu, v.y, 1);
    float2 vn;
    if (cz < res - 1 && lane < 31 && valid) {
        vn = make_float2(nx, ny);
    } else {
        int z1 = (cz + 1 == res) ? 0 : cz + 1;
        unsigned hz1 = hash_part(z1, fres, PRIME3);
        vn = __ldg(tab + ((hx + hy + hz1) & HASH_MASK));
    }

    if (valid) {
        int idx = (cx * res + cy) * res + cz;
        g_zp[(size_t)p.zp_base[li] + idx] = make_float4(v.x, v.y, vn.x, vn.y);
    }
}

// ---------------------------------------------------------------------------
// Fill z-paired hash tables for pow2-res levels (coalesced streams).
// ---------------------------------------------------------------------------
__global__ void __launch_bounds__(256)
fill_ztab_kernel(const float* __restrict__ tables, Params p, int total)
{
    int tid = blockIdx.x * blockDim.x + threadIdx.x;
    if (tid >= total) return;
    int slot   = tid >> HASH_BITS;
    unsigned s = tid & HASH_MASK;
    int level  = p.slot_level[slot];
    unsigned Dz = p.slot_dz[slot];

    const float2* tab = reinterpret_cast<const float2*>(tables)
                        + (size_t)level * TABLE_SIZE;
    float2 a = __ldg(tab + s);
    float2 b = __ldg(tab + ((s + Dz) & HASH_MASK));
    g_ztab[((size_t)slot << HASH_BITS) + s] = make_float4(a.x, a.y, b.x, b.y);
}

// ---------------------------------------------------------------------------
// Main kernel: ONE WARP PER POINT. lane = 2*level + yrow.
// Quad levels: lane pair reads consecutive 16B halves of one 32B entry.
// ---------------------------------------------------------------------------
__global__ void __launch_bounds__(256)
hash_encoding_kernel(const float* __restrict__ x,
                     const float* __restrict__ tables,
                     float* __restrict__ out,
                     Params p,
                     int n_points)
{
    int gtid = blockIdx.x * blockDim.x + threadIdx.x;
    int n    = gtid >> 5;
    if (n >= n_points) return;
    int lane  = gtid & 31;
    int level = lane >> 1;
    int yrow  = lane & 1;

    float xr = 0.f;
    if (lane < 3) xr = x[(size_t)n * 3 + lane];
    float xv[3];
    xv[0] = __shfl_sync(0xFFFFFFFFu, xr, 0);
    xv[1] = __shfl_sync(0xFFFFFFFFu, xr, 1);
    xv[2] = __shfl_sync(0xFFFFFFFFu, xr, 2);
#pragma unroll
    for (int d = 0; d < 3; d++) xv[d] = fminf(fmaxf(xv[d], -1.0f), 1.0f);

    const int   res  = p.res[level];
    const float fres = (float)res;

    int   c0[3], c1[3];
    float w[3][2];
#pragma unroll
    for (int d = 0; d < 3; d++) {
        float coord = xv[d] * fres;
        float cf    = floorf(coord);
        float lc    = coord - cf;
        int   ci    = (int)cf;
        w[d][0] = 1.0f - lc;
        w[d][1] = lc;
        int a = ci % res; if (a < 0) a += res;
        c0[d] = a;
        int b = a + 1;    if (b == res) b = 0;
        c1[d] = b;
    }

    float wx0 = w[0][0], wx1 = w[0][1];
    float wy  = w[1][yrow];
    float wz0 = w[2][0], wz1 = w[2][1];

    float part0, part1;

    if (level < N_QUAD) {
        // ---- quad path: 2 lane-pair-coalesced LDG.128 ----
        const float4* q = g_quad + (size_t)2 * p.quad_base[level];
        int rr = res;
        size_t i0 = (size_t)(c0[0] * rr + c0[1]) * rr + c0[2];
        size_t i1 = (size_t)(c1[0] * rr + c0[1]) * rr + c0[2];
        float4 a = __ldg(q + 2 * i0 + yrow);
        float4 b = __ldg(q + 2 * i1 + yrow);
        part0 = wy * (wx0 * (wz0 * a.x + wz1 * a.z) +
                      wx1 * (wz0 * b.x + wz1 * b.z));
        part1 = wy * (wx0 * (wz0 * a.y + wz1 * a.w) +
                      wx1 * (wz0 * b.y + wz1 * b.w));
    } else if (level < N_DENSE) {
        // ---- zpair dense path: 2 random LDG.128 (own y row) ----
        const float4* zp = g_zp + p.zp_base[level - N_QUAD];
        int rr = res;
        int cyr = yrow ? c1[1] : c0[1];
        float4 a = __ldg(zp + (size_t)(c0[0] * rr + cyr) * rr + c0[2]);
        float4 b = __ldg(zp + (size_t)(c1[0] * rr + cyr) * rr + c0[2]);
        part0 = wy * (wx0 * (wz0 * a.x + wz1 * a.z) +
                      wx1 * (wz0 * b.x + wz1 * b.z));
        part1 = wy * (wx0 * (wz0 * a.y + wz1 * a.w) +
                      wx1 * (wz0 * b.y + wz1 * b.w));
    } else {
        unsigned hp0[2], hp1y, hp2[2];
        hp0[0] = hash_part(c0[0], fres, 1u);
        hp0[1] = hash_part(c1[0], fres, 1u);
        hp1y   = hash_part(yrow ? c1[1] : c0[1], fres, PRIME2);
        hp2[0] = hash_part(c0[2], fres, PRIME3);
        const float2* tab = reinterpret_cast<const float2*>(tables)
                            + (size_t)level * TABLE_SIZE;

        bool paired = (p.pair_mask >> level) & 1u;
        if (paired && c0[2] != res - 1) {
            // ---- z-paired hash path: 2 random LDG.128 ----
            const float4* zt = g_ztab
                + ((size_t)p.pair_slot[level] << HASH_BITS);
            unsigned syz = hp1y + hp2[0];
            float4 a = __ldg(zt + ((hp0[0] + syz) & HASH_MASK));
            float4 b = __ldg(zt + ((hp0[1] + syz) & HASH_MASK));
            part0 = wy * (wx0 * (wz0 * a.x + wz1 * a.z) +
                          wx1 * (wz0 * b.x + wz1 * b.z));
            part1 = wy * (wx0 * (wz0 * a.y + wz1 * a.w) +
                          wx1 * (wz0 * b.y + wz1 * b.w));
        } else {
            // ---- general hashed path: 4 gathers (own y row) ----
            hp2[1] = hash_part(c1[2], fres, PRIME3);
            float2 f00 = __ldg(tab + ((hp0[0] + hp1y + hp2[0]) & HASH_MASK));
            float2 f01 = __ldg(tab + ((hp0[0] + hp1y + hp2[1]) & HASH_MASK));
            float2 f10 = __ldg(tab + ((hp0[1] + hp1y + hp2[0]) & HASH_MASK));
            float2 f11 = __ldg(tab + ((hp0[1] + hp1y + hp2[1]) & HASH_MASK));
            part0 = wy * (wx0 * (wz0 * f00.x + wz1 * f01.x) +
                          wx1 * (wz0 * f10.x + wz1 * f11.x));
            part1 = wy * (wx0 * (wz0 * f00.y + wz1 * f01.y) +
                          wx1 * (wz0 * f10.y + wz1 * f11.y));
        }
    }

    float tot0 = part0 + __shfl_xor_sync(0xFFFFFFFFu, part0, 1);
    float tot1 = part1 + __shfl_xor_sync(0xFFFFFFFFu, part1, 1);

    if (yrow == 0) {
        reinterpret_cast<float2*>(out)[(size_t)n * N_LEVELS + level] =
            make_float2(tot0, tot1);
    }
}

extern "C" void kernel_launch(void* const* d_in, const int* in_sizes, int n_in,
                              void* d_out, int out_size)
{
    const float* x      = (const float*)d_in[0];
    const float* tables = (const float*)d_in[1];
    float*       out    = (float*)d_out;

    int n_points = in_sizes[0] / 3;

    Params p;
    for (int i = 0; i < N_LEVELS; i++) {
        double r = 16.0 * pow(32.0, (double)i / 15.0);   // host libm pow
        p.res[i] = (int)r;
    }

    // quad levels 0..7
    int off = 0;
    p.qprefix[0] = 0;
    for (int i = 0; i < N_QUAD; i++) {
        p.quad_base[i] = off;
        int cnt = p.res[i] * p.res[i] * p.res[i];
        off += cnt;
        p.qprefix[i + 1] = p.qprefix[i] + cnt;
    }
    // zpair levels 8..9
    int zoff = 0;
    p.zpprefix[0] = 0;
    for (int i = 0; i < 2; i++) {
        p.zp_base[i] = zoff;
        int r = p.res[N_QUAD + i];
        int cnt = r * r * r;
        zoff += cnt;
        p.zpprefix[i + 1] = p.zpprefix[i] + cnt;
    }

    p.pair_mask = 0;
    p.n_paired  = 0;
    for (int i = 0; i < N_LEVELS; i++) p.pair_slot[i] = 0;
    for (int lvl = N_DENSE; lvl < N_LEVELS && p.n_paired < MAX_PAIRED; lvl++) {
        int r = p.res[lvl];
        if ((r & (r - 1)) == 0 && r <= 131072) {
            unsigned step = 131072u / (unsigned)r;
            p.pair_mask |= (1u << lvl);
            p.pair_slot[lvl] = p.n_paired;
            p.slot_level[p.n_paired] = lvl;
            p.slot_dz[p.n_paired] = PRIME3 * step;
            p.n_paired++;
        }
    }

    int threads = 256;

    int total_q = p.qprefix[N_QUAD];
    fill_quad_kernel<<<(total_q + threads - 1) / threads, threads>>>(
        tables, p, total_q);

    int total_zp = p.zpprefix[2];
    fill_zp_kernel<<<(total_zp + threads - 1) / threads, threads>>>(
        tables, p, total_zp);

    if (p.n_paired > 0) {
        int total_z = p.n_paired * (int)TABLE_SIZE;
        fill_ztab_kernel<<<(total_z + threads - 1) / threads, threads>>>(
            tables, p, total_z);
    }

    long long total = (long long)n_points * 32;
    int blocks = (int)((total + threads - 1) / threads);
    hash_encoding_kernel<<<blocks, threads>>>(x, tables, out, p, n_points);
}

// round 7
// speedup vs baseline: 1.2509x; 1.2509x over previous
#include <cuda_runtime.h>
#include <cuda_fp16.h>
#include <math.h>
#include <stdint.h>

#define N_LEVELS   16
#define N_DQ       9            // levels 0..8: dense fp16 quad grid
#define HASH_BITS  19
#define TABLE_SIZE (1u << HASH_BITS)
#define HASH_MASK  (TABLE_SIZE - 1u)
#define PRIME2     2654435761u
#define PRIME3     805459861u
#define FSCALE     256.0f
#define INV_FSCALE (1.0f / 256.0f)

// Dense fp16 quad grid, levels 0..8: entry(cx,cy,cz) = 16B =
//   {h2(y0z0), h2(y0z1), h2(y1z0), h2(y1z1)}, h2 = half2(256*f0, 256*f1)
#define DQ_CAP 2200000
__device__ uint4 g_dq[DQ_CAP];                       // ~35 MB

// Two-delta fp16 z-paired hash tables, 5 levels (9,10,11,13,14) x 2 deltas:
//   T[s] = { h2(tab[s]), h2(tab[(s+D)&M]) }  (8B)
#define N_ZP 5
__device__ uint2 g_zp2[(size_t)(2 * N_ZP) << HASH_BITS];   // ~42 MB

// Pow2-res fp16 quad hash tables, 2 levels (12,15):
//   T[s] = { h2(tab[s]), h2(tab[s+Dz]), h2(tab[s+Dy]), h2(tab[s+Dy+Dz]) }
#define N_Q2 2
__device__ uint4 g_q2[(size_t)N_Q2 << HASH_BITS];          // ~17 MB

struct Params {
    int      res[N_LEVELS];
    int      kind[N_LEVELS];     // 0 dense quad, 1 two-delta zpair, 2 pow2 quad
    int      base[N_LEVELS];     // dense: entry offset; zp: (li*2)<<19; q2: slot<<19
    unsigned dA[N_LEVELS];       // zp: P3*d       q2: Dz = P3*step
    unsigned dB[N_LEVELS];       // zp: P3*(d+1)   q2: Dy = P2*step
    int      dq_prefix[N_DQ + 1];
    int      zp_levels[N_ZP];
    int      q2_levels[N_Q2];
};

// XLA-GPU lowers f32 divide to div.full.f32 (approx). The hash trunc
// amplifies 1-ulp differences into wrong indices; reproduce the instruction.
__device__ __forceinline__ float div_full(float a, float b) {
    float r;
    asm("div.full.f32 %0, %1, %2;" : "=f"(r) : "f"(a), "f"(b));
    return r;
}

__device__ __forceinline__ unsigned hash_part(int c, float fres, unsigned prime) {
    float cfrac = div_full((float)c, fres);
    float qf = __fmul_rn(__fmul_rn(__fadd_rn(cfrac, 1.0f), 0.5f), 262144.0f);
    unsigned q = (unsigned)qf;            // positive -> trunc == astype(int64)
    return q * prime;                      // uint32 wrap OK: 2^19 | 2^32
}

__device__ __forceinline__ unsigned pack_h2(float2 v) {
    __half2 h = __floats2half2_rn(v.x * FSCALE, v.y * FSCALE);
    return *reinterpret_cast<unsigned*>(&h);
}
__device__ __forceinline__ float2 unpack_h2(unsigned u) {
    __half2 h = *reinterpret_cast<__half2*>(&u);
    return __half22float2(h);
}

// ---------------------------------------------------------------------------
// Fill dense fp16 quad grid (levels 0..8): thread per corner.
// Gathers (y,z) and (y+1,z); z+1 values via shfl from lane+1 (cz fastest);
// boundary lanes re-gather. One coalesced 16B store.
// ---------------------------------------------------------------------------
__global__ void __launch_bounds__(256)
fill_dq_kernel(const float* __restrict__ tables, Params p, int total)
{
    int tid0 = blockIdx.x * blockDim.x + threadIdx.x;
    bool valid = tid0 < total;
    int tid = valid ? tid0 : (total - 1);

    int level = 0;
#pragma unroll
    for (int i = 0; i < N_DQ; i++)
        if (tid >= p.dq_prefix[i + 1]) level = i + 1;

    int r   = tid - p.dq_prefix[level];
    int res = p.res[level];
    int cz = r % res;
    int t  = r / res;
    int cy = t % res;
    int cx = t / res;
    int cy1 = (cy + 1 == res) ? 0 : cy + 1;

    float fres = (float)res;
    unsigned hx  = hash_part(cx,  fres, 1u);
    unsigned hy  = hash_part(cy,  fres, PRIME2);
    unsigned hy1 = hash_part(cy1, fres, PRIME2);
    unsigned hz  = hash_part(cz,  fres, PRIME3);

    const float2* tab = reinterpret_cast<const float2*>(tables)
                        + (size_t)level * TABLE_SIZE;
    float2 v00 = __ldg(tab + ((hx + hy  + hz) & HASH_MASK));
    float2 v10 = __ldg(tab + ((hx + hy1 + hz) & HASH_MASK));

    int lane = threadIdx.x & 31;
    float a0 = __shfl_down_sync(0xFFFFFFFFu, v00.x, 1);
    float a1 = __shfl_down_sync(0xFFFFFFFFu, v00.y, 1);
    float b0 = __shfl_down_sync(0xFFFFFFFFu, v10.x, 1);
    float b1 = __shfl_down_sync(0xFFFFFFFFu, v10.y, 1);
    float2 v01, v11;
    if (valid && cz < res - 1 && lane < 31 && tid0 + 1 < total) {
        v01 = make_float2(a0, a1);
        v11 = make_float2(b0, b1);
    } else {
        int z1 = (cz + 1 == res) ? 0 : cz + 1;
        unsigned hz1 = hash_part(z1, fres, PRIME3);
        v01 = __ldg(tab + ((hx + hy  + hz1) & HASH_MASK));
        v11 = __ldg(tab + ((hx + hy1 + hz1) & HASH_MASK));
    }

    if (valid) {
        uint4 e;
        e.x = pack_h2(v00);   // y0 z0
        e.y = pack_h2(v01);   // y0 z1
        e.z = pack_h2(v10);   // y1 z0
        e.w = pack_h2(v11);   // y1 z1
        g_dq[(size_t)p.base[level] + ((cx * res + cy) * res + cz)] = e;
    }
}

// ---------------------------------------------------------------------------
// Fill two-delta fp16 zpair tables: fully coalesced (s and s+D both stream).
// ---------------------------------------------------------------------------
__global__ void __launch_bounds__(256)
fill_zp2_kernel(const float* __restrict__ tables, Params p, int total)
{
    int tid = blockIdx.x * blockDim.x + threadIdx.x;
    if (tid >= total) return;
    int slot   = tid >> HASH_BITS;
    unsigned s = tid & HASH_MASK;
    int li  = slot >> 1;
    int lvl = p.zp_levels[li];
    unsigned D = (slot & 1) ? p.dB[lvl] : p.dA[lvl];

    const float2* tab = reinterpret_cast<const float2*>(tables)
                        + (size_t)lvl * TABLE_SIZE;
    float2 a = __ldg(tab + s);
    float2 b = __ldg(tab + ((s + D) & HASH_MASK));
    uint2 e;
    e.x = pack_h2(a);
    e.y = pack_h2(b);
    g_zp2[((size_t)slot << HASH_BITS) + s] = e;
}

// ---------------------------------------------------------------------------
// Fill pow2 fp16 quad tables (levels 12,15): fully coalesced.
// ---------------------------------------------------------------------------
__global__ void __launch_bounds__(256)
fill_q2_kernel(const float* __restrict__ tables, Params p, int total)
{
    int tid = blockIdx.x * blockDim.x + threadIdx.x;
    if (tid >= total) return;
    int slot   = tid >> HASH_BITS;
    unsigned s = tid & HASH_MASK;
    int lvl = p.q2_levels[slot];
    unsigned Dz = p.dA[lvl];
    unsigned Dy = p.dB[lvl];

    const float2* tab = reinterpret_cast<const float2*>(tables)
                        + (size_t)lvl * TABLE_SIZE;
    uint4 e;
    e.x = pack_h2(__ldg(tab + s));                           // y0 z0
    e.y = pack_h2(__ldg(tab + ((s + Dz) & HASH_MASK)));      // y0 z1
    e.z = pack_h2(__ldg(tab + ((s + Dy) & HASH_MASK)));      // y1 z0
    e.w = pack_h2(__ldg(tab + ((s + Dy + Dz) & HASH_MASK))); // y1 z1
    g_q2[((size_t)slot << HASH_BITS) + s] = e;
}

// ---------------------------------------------------------------------------
// Main kernel: thread per (point, level), level fastest (16 lanes/point).
// ---------------------------------------------------------------------------
__global__ void __launch_bounds__(256)
hash_encoding_kernel(const float* __restrict__ x,
                     const float* __restrict__ tables,
                     float* __restrict__ out,
                     Params p,
                     int n_points)
{
    int tid = blockIdx.x * blockDim.x + threadIdx.x;
    int n     = tid >> 4;
    int level = tid & 15;
    if (n >= n_points) return;

    float xv[3];
#pragma unroll
    for (int d = 0; d < 3; d++)
        xv[d] = fminf(fmaxf(__ldg(&x[(size_t)n * 3 + d]), -1.0f), 1.0f);

    const int   res  = p.res[level];
    const float fres = (float)res;

    int   c0[3], c1[3];
    float w[3][2];
#pragma unroll
    for (int d = 0; d < 3; d++) {
        float coord = xv[d] * fres;
        float cf    = floorf(coord);
        float lc    = coord - cf;
        int   ci    = (int)cf;
        w[d][0] = 1.0f - lc;
        w[d][1] = lc;
        int a = ci % res; if (a < 0) a += res;
        c0[d] = a;
        int b = a + 1;    if (b == res) b = 0;
        c1[d] = b;
    }

    float wx0 = w[0][0], wx1 = w[0][1];
    float wy0 = w[1][0], wy1 = w[1][1];
    float wz0 = w[2][0], wz1 = w[2][1];

    float acc0, acc1;
    int kind = p.kind[level];

    if (kind == 0) {
        // ---- dense fp16 quad: 2 LDG.128, each = 4 corners ----
        const uint4* dq = g_dq + p.base[level];
        int rr = res;
        uint4 e0 = __ldg(dq + ((c0[0] * rr + c0[1]) * rr + c0[2]));
        uint4 e1 = __ldg(dq + ((c1[0] * rr + c0[1]) * rr + c0[2]));
        float2 a00 = unpack_h2(e0.x), a01 = unpack_h2(e0.y);
        float2 a10 = unpack_h2(e0.z), a11 = unpack_h2(e0.w);
        float2 b00 = unpack_h2(e1.x), b01 = unpack_h2(e1.y);
        float2 b10 = unpack_h2(e1.z), b11 = unpack_h2(e1.w);
        acc0 = (wx0 * (wy0 * (wz0 * a00.x + wz1 * a01.x) +
                       wy1 * (wz0 * a10.x + wz1 * a11.x)) +
                wx1 * (wy0 * (wz0 * b00.x + wz1 * b01.x) +
                       wy1 * (wz0 * b10.x + wz1 * b11.x))) * INV_FSCALE;
        acc1 = (wx0 * (wy0 * (wz0 * a00.y + wz1 * a01.y) +
                       wy1 * (wz0 * a10.y + wz1 * a11.y)) +
                wx1 * (wy0 * (wz0 * b00.y + wz1 * b01.y) +
                       wy1 * (wz0 * b10.y + wz1 * b11.y))) * INV_FSCALE;
    } else {
        unsigned hx0 = hash_part(c0[0], fres, 1u);
        unsigned hx1 = hash_part(c1[0], fres, 1u);
        unsigned hy0 = hash_part(c0[1], fres, PRIME2);
        unsigned hy1 = hash_part(c1[1], fres, PRIME2);
        unsigned hz0 = hash_part(c0[2], fres, PRIME3);
        unsigned hz1 = hash_part(c1[2], fres, PRIME3);
        unsigned diffz = hz1 - hz0;
        unsigned diffy = hy1 - hy0;

        bool done = false;
        if (kind == 1) {
            int t = -1;
            if (diffz == p.dA[level])      t = 0;
            else if (diffz == p.dB[level]) t = 1;
            if (t >= 0) {
                const uint2* zt = g_zp2 + ((size_t)p.base[level]
                                           + ((size_t)t << HASH_BITS));
                unsigned s00 = (hx0 + hy0 + hz0) & HASH_MASK;
                unsigned s01 = (hx0 + hy1 + hz0) & HASH_MASK;
                unsigned s10 = (hx1 + hy0 + hz0) & HASH_MASK;
                unsigned s11 = (hx1 + hy1 + hz0) & HASH_MASK;
                uint2 e00 = __ldg(zt + s00);
                uint2 e01 = __ldg(zt + s01);
                uint2 e10 = __ldg(zt + s10);
                uint2 e11 = __ldg(zt + s11);
                float2 p00a = unpack_h2(e00.x), p00b = unpack_h2(e00.y);
                float2 p01a = unpack_h2(e01.x), p01b = unpack_h2(e01.y);
                float2 p10a = unpack_h2(e10.x), p10b = unpack_h2(e10.y);
                float2 p11a = unpack_h2(e11.x), p11b = unpack_h2(e11.y);
                acc0 = (wx0 * (wy0 * (wz0 * p00a.x + wz1 * p00b.x) +
                               wy1 * (wz0 * p01a.x + wz1 * p01b.x)) +
                        wx1 * (wy0 * (wz0 * p10a.x + wz1 * p10b.x) +
                               wy1 * (wz0 * p11a.x + wz1 * p11b.x))) * INV_FSCALE;
                acc1 = (wx0 * (wy0 * (wz0 * p00a.y + wz1 * p00b.y) +
                               wy1 * (wz0 * p01a.y + wz1 * p01b.y)) +
                        wx1 * (wy0 * (wz0 * p10a.y + wz1 * p10b.y) +
                               wy1 * (wz0 * p11a.y + wz1 * p11b.y))) * INV_FSCALE;
                done = true;
            }
        } else {
            if (diffz == p.dA[level] && diffy == p.dB[level]) {
                const uint4* qt = g_q2 + (size_t)p.base[level];
                unsigned s0 = (hx0 + hy0 + hz0) & HASH_MASK;
                unsigned s1 = (hx1 + hy0 + hz0) & HASH_MASK;
                uint4 e0 = __ldg(qt + s0);
                uint4 e1 = __ldg(qt + s1);
                float2 a00 = unpack_h2(e0.x), a01 = unpack_h2(e0.y);
                float2 a10 = unpack_h2(e0.z), a11 = unpack_h2(e0.w);
                float2 b00 = unpack_h2(e1.x), b01 = unpack_h2(e1.y);
                float2 b10 = unpack_h2(e1.z), b11 = unpack_h2(e1.w);
                acc0 = (wx0 * (wy0 * (wz0 * a00.x + wz1 * a01.x) +
                               wy1 * (wz0 * a10.x + wz1 * a11.x)) +
                        wx1 * (wy0 * (wz0 * b00.x + wz1 * b01.x) +
                               wy1 * (wz0 * b10.x + wz1 * b11.x))) * INV_FSCALE;
                acc1 = (wx0 * (wy0 * (wz0 * a00.y + wz1 * a01.y) +
                               wy1 * (wz0 * a10.y + wz1 * a11.y)) +
                        wx1 * (wy0 * (wz0 * b00.y + wz1 * b01.y) +
                               wy1 * (wz0 * b10.y + wz1 * b11.y))) * INV_FSCALE;
                done = true;
            }
        }

        if (!done) {
            // ---- exact f32 fallback: 8 gathers (wraps / step anomalies) ----
            const float2* tab = reinterpret_cast<const float2*>(tables)
                                + (size_t)level * TABLE_SIZE;
            float2 f000 = __ldg(tab + ((hx0 + hy0 + hz0) & HASH_MASK));
            float2 f001 = __ldg(tab + ((hx0 + hy0 + hz1) & HASH_MASK));
            float2 f010 = __ldg(tab + ((hx0 + hy1 + hz0) & HASH_MASK));
            float2 f011 = __ldg(tab + ((hx0 + hy1 + hz1) & HASH_MASK));
            float2 f100 = __ldg(tab + ((hx1 + hy0 + hz0) & HASH_MASK));
            float2 f101 = __ldg(tab + ((hx1 + hy0 + hz1) & HASH_MASK));
            float2 f110 = __ldg(tab + ((hx1 + hy1 + hz0) & HASH_MASK));
            float2 f111 = __ldg(tab + ((hx1 + hy1 + hz1) & HASH_MASK));
            acc0 = wx0 * (wy0 * (wz0 * f000.x + wz1 * f001.x) +
                          wy1 * (wz0 * f010.x + wz1 * f011.x)) +
                   wx1 * (wy0 * (wz0 * f100.x + wz1 * f101.x) +
                          wy1 * (wz0 * f110.x + wz1 * f111.x));
            acc1 = wx0 * (wy0 * (wz0 * f000.y + wz1 * f001.y) +
                          wy1 * (wz0 * f010.y + wz1 * f011.y)) +
                   wx1 * (wy0 * (wz0 * f100.y + wz1 * f101.y) +
                          wy1 * (wz0 * f110.y + wz1 * f111.y));
        }
    }

    reinterpret_cast<float2*>(out)[(size_t)n * N_LEVELS + level] =
        make_float2(acc0, acc1);
}

extern "C" void kernel_launch(void* const* d_in, const int* in_sizes, int n_in,
                              void* d_out, int out_size)
{
    const float* x      = (const float*)d_in[0];
    const float* tables = (const float*)d_in[1];
    float*       out    = (float*)d_out;

    int n_points = in_sizes[0] / 3;

    Params p;
    for (int i = 0; i < N_LEVELS; i++) {
        double r = 16.0 * pow(32.0, (double)i / 15.0);   // host libm pow
        p.res[i] = (int)r;
    }

    // Dense quad levels 0..8
    int off = 0;
    p.dq_prefix[0] = 0;
    for (int i = 0; i < N_DQ; i++) {
        p.kind[i] = 0;
        p.base[i] = off;
        p.dA[i] = 0; p.dB[i] = 0;
        int cnt = p.res[i] * p.res[i] * p.res[i];
        off += cnt;
        p.dq_prefix[i + 1] = p.dq_prefix[i] + cnt;
    }

    // Classify remaining levels: pow2 -> quad hash table, else two-delta zpair
    int n_zp = 0, n_q2 = 0;
    for (int lvl = N_DQ; lvl < N_LEVELS; lvl++) {
        int r = p.res[lvl];
        if ((r & (r - 1)) == 0) {
            unsigned step = 131072u / (unsigned)r;       // exact
            p.kind[lvl] = 2;
            p.base[lvl] = n_q2 << HASH_BITS;
            p.dA[lvl] = PRIME3 * step;                   // Dz
            p.dB[lvl] = PRIME2 * step;                   // Dy
            p.q2_levels[n_q2++] = lvl;
        } else {
            unsigned d = 131072u / (unsigned)r;          // floor
            p.kind[lvl] = 1;
            p.base[lvl] = (n_zp * 2) << HASH_BITS;
            p.dA[lvl] = PRIME3 * d;
            p.dB[lvl] = PRIME3 * (d + 1);
            p.zp_levels[n_zp++] = lvl;
        }
    }

    int threads = 256;

    int total_dq = p.dq_prefix[N_DQ];
    fill_dq_kernel<<<(total_dq + threads - 1) / threads, threads>>>(
        tables, p, total_dq);

    if (n_zp > 0) {
        int total_zp = (n_zp * 2) << HASH_BITS;
        fill_zp2_kernel<<<(total_zp + threads - 1) / threads, threads>>>(
            tables, p, total_zp);
    }
    if (n_q2 > 0) {
        int total_q2 = n_q2 << HASH_BITS;
        fill_q2_kernel<<<(total_q2 + threads - 1) / threads, threads>>>(
            tables, p, total_q2);
    }

    long long total = (long long)n_points * 16;
    int blocks = (int)((total + threads - 1) / threads);
    hash_encoding_kernel<<<blocks, threads>>>(x, tables, out, p, n_points);
}

// round 9
// speedup vs baseline: 1.5274x; 1.2210x over previous
#include <cuda_runtime.h>
#include <cuda_fp16.h>
#include <math.h>
#include <stdint.h>

#define N_LEVELS   16
#define N_DQ       9            // levels 0..8: dense fp16 quad grid
#define HASH_BITS  19
#define TABLE_SIZE (1u << HASH_BITS)
#define HASH_MASK  (TABLE_SIZE - 1u)
#define PRIME2     2654435761u
#define PRIME3     805459861u
#define FSCALE     256.0f
#define INV_FSCALE (1.0f / 256.0f)

// Dense fp16 quad grid, levels 0..8: entry(cx,cy,cz) = 16B =
//   {h2(y0z0), h2(y0z1), h2(y1z0), h2(y1z1)}, h2 = half2(256*f0, 256*f1)
#define DQ_CAP 2200000
__device__ uint4 g_dq[DQ_CAP];                       // ~35 MB

// Two-delta fp16 z-paired hash tables, 5 levels (9,10,11,13,14) x 2 deltas:
//   T[s] = { h2(tab[s]), h2(tab[(s+D)&M]) }  (8B)
#define N_ZP 5
__device__ uint2 g_zp2[(size_t)(2 * N_ZP) << HASH_BITS];   // ~42 MB

// Pow2-res fp16 quad hash tables, 2 levels (12,15):
//   T[s] = { h2(tab[s]), h2(tab[s+Dz]), h2(tab[s+Dy]), h2(tab[s+Dy+Dz]) }
#define N_Q2 2
__device__ uint4 g_q2[(size_t)N_Q2 << HASH_BITS];          // ~17 MB

struct Params {
    int      res[N_LEVELS];
    int      kind[N_LEVELS];     // 0 dense quad, 1 two-delta zpair, 2 pow2 quad
    int      base[N_LEVELS];
    unsigned dA[N_LEVELS];       // zp: P3*d       q2: Dz = P3*step
    unsigned dB[N_LEVELS];       // zp: P3*(d+1)   q2: Dy = P2*step
    int      dq_prefix[N_DQ + 1];
    int      zp_levels[N_ZP];
    int      q2_levels[N_Q2];
};

// XLA-GPU lowers f32 divide to div.full.f32 (approx). The hash trunc
// amplifies 1-ulp differences into wrong indices; reproduce the instruction.
__device__ __forceinline__ float div_full(float a, float b) {
    float r;
    asm("div.full.f32 %0, %1, %2;" : "=f"(r) : "f"(a), "f"(b));
    return r;
}

__device__ __forceinline__ unsigned hash_part(int c, float fres, unsigned prime) {
    float cfrac = div_full((float)c, fres);
    // (cfrac+1)*0.5*2^18 == (cfrac+1)*2^17 exactly (power-of-2 scalings exact)
    float qf = __fmul_rn(__fadd_rn(cfrac, 1.0f), 131072.0f);
    unsigned q = (unsigned)qf;            // positive -> trunc == astype(int64)
    return q * prime;                      // uint32 wrap OK: 2^19 | 2^32
}

__device__ __forceinline__ unsigned pack_h2(float2 v) {
    __half2 h = __floats2half2_rn(v.x * FSCALE, v.y * FSCALE);
    return *reinterpret_cast<unsigned*>(&h);
}
__device__ __forceinline__ float2 unpack_h2(unsigned u) {
    __half2 h = *reinterpret_cast<__half2*>(&u);
    return __half22float2(h);
}

// ---------------------------------------------------------------------------
// Fill dense fp16 quad grid (levels 0..8): thread per corner.
// ---------------------------------------------------------------------------
__global__ void __launch_bounds__(256)
fill_dq_kernel(const float* __restrict__ tables, Params p, int total)
{
    int tid0 = blockIdx.x * blockDim.x + threadIdx.x;
    bool valid = tid0 < total;
    int tid = valid ? tid0 : (total - 1);

    int level = 0;
#pragma unroll
    for (int i = 0; i < N_DQ; i++)
        if (tid >= p.dq_prefix[i + 1]) level = i + 1;

    int r   = tid - p.dq_prefix[level];
    int res = p.res[level];
    int cz = r % res;
    int t  = r / res;
    int cy = t % res;
    int cx = t / res;
    int cy1 = (cy + 1 == res) ? 0 : cy + 1;

    float fres = (float)res;
    unsigned hx  = hash_part(cx,  fres, 1u);
    unsigned hy  = hash_part(cy,  fres, PRIME2);
    unsigned hy1 = hash_part(cy1, fres, PRIME2);
    unsigned hz  = hash_part(cz,  fres, PRIME3);

    const float2* tab = reinterpret_cast<const float2*>(tables)
                        + (size_t)level * TABLE_SIZE;
    float2 v00 = __ldg(tab + ((hx + hy  + hz) & HASH_MASK));
    float2 v10 = __ldg(tab + ((hx + hy1 + hz) & HASH_MASK));

    int lane = threadIdx.x & 31;
    float a0 = __shfl_down_sync(0xFFFFFFFFu, v00.x, 1);
    float a1 = __shfl_down_sync(0xFFFFFFFFu, v00.y, 1);
    float b0 = __shfl_down_sync(0xFFFFFFFFu, v10.x, 1);
    float b1 = __shfl_down_sync(0xFFFFFFFFu, v10.y, 1);
    float2 v01, v11;
    if (valid && cz < res - 1 && lane < 31 && tid0 + 1 < total) {
        v01 = make_float2(a0, a1);
        v11 = make_float2(b0, b1);
    } else {
        int z1 = (cz + 1 == res) ? 0 : cz + 1;
        unsigned hz1 = hash_part(z1, fres, PRIME3);
        v01 = __ldg(tab + ((hx + hy  + hz1) & HASH_MASK));
        v11 = __ldg(tab + ((hx + hy1 + hz1) & HASH_MASK));
    }

    if (valid) {
        uint4 e;
        e.x = pack_h2(v00);
        e.y = pack_h2(v01);
        e.z = pack_h2(v10);
        e.w = pack_h2(v11);
        g_dq[(size_t)p.base[level] + ((cx * res + cy) * res + cz)] = e;
    }
}

// ---------------------------------------------------------------------------
// Fill two-delta fp16 zpair tables: fully coalesced.
// ---------------------------------------------------------------------------
__global__ void __launch_bounds__(256)
fill_zp2_kernel(const float* __restrict__ tables, Params p, int total)
{
    int tid = blockIdx.x * blockDim.x + threadIdx.x;
    if (tid >= total) return;
    int slot   = tid >> HASH_BITS;
    unsigned s = tid & HASH_MASK;
    int li  = slot >> 1;
    int lvl = p.zp_levels[li];
    unsigned D = (slot & 1) ? p.dB[lvl] : p.dA[lvl];

    const float2* tab = reinterpret_cast<const float2*>(tables)
                        + (size_t)lvl * TABLE_SIZE;
    float2 a = __ldg(tab + s);
    float2 b = __ldg(tab + ((s + D) & HASH_MASK));
    uint2 e;
    e.x = pack_h2(a);
    e.y = pack_h2(b);
    g_zp2[((size_t)slot << HASH_BITS) + s] = e;
}

// ---------------------------------------------------------------------------
// Fill pow2 fp16 quad tables (levels 12,15): fully coalesced.
// ---------------------------------------------------------------------------
__global__ void __launch_bounds__(256)
fill_q2_kernel(const float* __restrict__ tables, Params p, int total)
{
    int tid = blockIdx.x * blockDim.x + threadIdx.x;
    if (tid >= total) return;
    int slot   = tid >> HASH_BITS;
    unsigned s = tid & HASH_MASK;
    int lvl = p.q2_levels[slot];
    unsigned Dz = p.dA[lvl];
    unsigned Dy = p.dB[lvl];

    const float2* tab = reinterpret_cast<const float2*>(tables)
                        + (size_t)lvl * TABLE_SIZE;
    uint4 e;
    e.x = pack_h2(__ldg(tab + s));
    e.y = pack_h2(__ldg(tab + ((s + Dz) & HASH_MASK)));
    e.z = pack_h2(__ldg(tab + ((s + Dy) & HASH_MASK)));
    e.w = pack_h2(__ldg(tab + ((s + Dy + Dz) & HASH_MASK)));
    g_q2[((size_t)slot << HASH_BITS) + s] = e;
}

// ---------------------------------------------------------------------------
// Main kernel: block = 32 points x 16 levels (512 threads).
// warp w = level w (BRANCH-UNIFORM), lane = point. Output via smem transpose.
// ---------------------------------------------------------------------------
__global__ void __launch_bounds__(512)
hash_encoding_kernel(const float* __restrict__ x,
                     const float* __restrict__ tables,
                     float* __restrict__ out,
                     Params p,
                     int n_points)
{
    __shared__ float  xs[96];                 // 32 points x 3 coords
    __shared__ float2 outs[32][N_LEVELS + 1]; // +1 pad vs bank conflicts

    int tid = threadIdx.x;
    int n0  = blockIdx.x * 32;

    if (tid < 96) {
        int gi = n0 * 3 + tid;
        xs[tid] = (gi < n_points * 3) ? x[gi] : 0.0f;
    }
    __syncthreads();

    int level = tid >> 5;        // warp index == level (uniform per warp)
    int l     = tid & 31;        // point within block
    int n     = n0 + l;

    float xv[3];
#pragma unroll
    for (int d = 0; d < 3; d++)
        xv[d] = fminf(fmaxf(xs[l * 3 + d], -1.0f), 1.0f);

    const int   res  = p.res[level];
    const float fres = (float)res;

    int   c0[3], c1[3];
    float w[3][2];
#pragma unroll
    for (int d = 0; d < 3; d++) {
        float coord = xv[d] * fres;
        float cf    = floorf(coord);
        float lc    = coord - cf;
        int   ci    = (int)cf;
        w[d][0] = 1.0f - lc;
        w[d][1] = lc;
        // ci in [-res, res] -> floor-mod via predicated adds (no int div)
        int a = ci;
        if (a < 0)    a += res;
        if (a >= res) a -= res;
        c0[d] = a;
        int b = a + 1; if (b == res) b = 0;
        c1[d] = b;
    }

    float wx0 = w[0][0], wx1 = w[0][1];
    float wy0 = w[1][0], wy1 = w[1][1];
    float wz0 = w[2][0], wz1 = w[2][1];

    float acc0 = 0.0f, acc1 = 0.0f;
    int kind = p.kind[level];

    if (kind == 0) {
        // ---- dense fp16 quad: 2 LDG.128 = 8 corners ----
        const uint4* dq = g_dq + p.base[level];
        int rr = res;
        uint4 e0 = __ldg(dq + ((c0[0] * rr + c0[1]) * rr + c0[2]));
        uint4 e1 = __ldg(dq + ((c1[0] * rr + c0[1]) * rr + c0[2]));
        float2 a00 = unpack_h2(e0.x), a01 = unpack_h2(e0.y);
        float2 a10 = unpack_h2(e0.z), a11 = unpack_h2(e0.w);
        float2 b00 = unpack_h2(e1.x), b01 = unpack_h2(e1.y);
        float2 b10 = unpack_h2(e1.z), b11 = unpack_h2(e1.w);
        acc0 = (wx0 * (wy0 * (wz0 * a00.x + wz1 * a01.x) +
                       wy1 * (wz0 * a10.x + wz1 * a11.x)) +
                wx1 * (wy0 * (wz0 * b00.x + wz1 * b01.x) +
                       wy1 * (wz0 * b10.x + wz1 * b11.x))) * INV_FSCALE;
        acc1 = (wx0 * (wy0 * (wz0 * a00.y + wz1 * a01.y) +
                       wy1 * (wz0 * a10.y + wz1 * a11.y)) +
                wx1 * (wy0 * (wz0 * b00.y + wz1 * b01.y) +
                       wy1 * (wz0 * b10.y + wz1 * b11.y))) * INV_FSCALE;
    } else {
        unsigned hx0 = hash_part(c0[0], fres, 1u);
        unsigned hx1 = hash_part(c1[0], fres, 1u);
        unsigned hy0 = hash_part(c0[1], fres, PRIME2);
        unsigned hy1 = hash_part(c1[1], fres, PRIME2);
        unsigned hz0 = hash_part(c0[2], fres, PRIME3);
        unsigned hz1 = hash_part(c1[2], fres, PRIME3);
        unsigned diffz = hz1 - hz0;
        unsigned diffy = hy1 - hy0;

        bool done = false;
        if (kind == 1) {
            int t = -1;
            if (diffz == p.dA[level])      t = 0;
            else if (diffz == p.dB[level]) t = 1;
            if (t >= 0) {
                const uint2* zt = g_zp2 + ((size_t)p.base[level]
                                           + ((size_t)t << HASH_BITS));
                uint2 e00 = __ldg(zt + ((hx0 + hy0 + hz0) & HASH_MASK));
                uint2 e01 = __ldg(zt + ((hx0 + hy1 + hz0) & HASH_MASK));
                uint2 e10 = __ldg(zt + ((hx1 + hy0 + hz0) & HASH_MASK));
                uint2 e11 = __ldg(zt + ((hx1 + hy1 + hz0) & HASH_MASK));
                float2 p00a = unpack_h2(e00.x), p00b = unpack_h2(e00.y);
                float2 p01a = unpack_h2(e01.x), p01b = unpack_h2(e01.y);
                float2 p10a = unpack_h2(e10.x), p10b = unpack_h2(e10.y);
                float2 p11a = unpack_h2(e11.x), p11b = unpack_h2(e11.y);
                acc0 = (wx0 * (wy0 * (wz0 * p00a.x + wz1 * p00b.x) +
                               wy1 * (wz0 * p01a.x + wz1 * p01b.x)) +
                        wx1 * (wy0 * (wz0 * p10a.x + wz1 * p10b.x) +
                               wy1 * (wz0 * p11a.x + wz1 * p11b.x))) * INV_FSCALE;
                acc1 = (wx0 * (wy0 * (wz0 * p00a.y + wz1 * p00b.y) +
                               wy1 * (wz0 * p01a.y + wz1 * p01b.y)) +
                        wx1 * (wy0 * (wz0 * p10a.y + wz1 * p10b.y) +
                               wy1 * (wz0 * p11a.y + wz1 * p11b.y))) * INV_FSCALE;
                done = true;
            }
        } else {
            if (diffz == p.dA[level] && diffy == p.dB[level]) {
                const uint4* qt = g_q2 + (size_t)p.base[level];
                uint4 e0 = __ldg(qt + ((hx0 + hy0 + hz0) & HASH_MASK));
                uint4 e1 = __ldg(qt + ((hx1 + hy0 + hz0) & HASH_MASK));
                float2 a00 = unpack_h2(e0.x), a01 = unpack_h2(e0.y);
                float2 a10 = unpack_h2(e0.z), a11 = unpack_h2(e0.w);
                float2 b00 = unpack_h2(e1.x), b01 = unpack_h2(e1.y);
                float2 b10 = unpack_h2(e1.z), b11 = unpack_h2(e1.w);
                acc0 = (wx0 * (wy0 * (wz0 * a00.x + wz1 * a01.x) +
                               wy1 * (wz0 * a10.x + wz1 * a11.x)) +
                        wx1 * (wy0 * (wz0 * b00.x + wz1 * b01.x) +
                               wy1 * (wz0 * b10.x + wz1 * b11.x))) * INV_FSCALE;
                acc1 = (wx0 * (wy0 * (wz0 * a00.y + wz1 * a01.y) +
                               wy1 * (wz0 * a10.y + wz1 * a11.y)) +
                        wx1 * (wy0 * (wz0 * b00.y + wz1 * b01.y) +
                               wy1 * (wz0 * b10.y + wz1 * b11.y))) * INV_FSCALE;
                done = true;
            }
        }

        if (!done) {
            // ---- exact f32 fallback: 8 gathers (wraps / step anomalies) ----
            const float2* tab = reinterpret_cast<const float2*>(tables)
                                + (size_t)level * TABLE_SIZE;
            float2 f000 = __ldg(tab + ((hx0 + hy0 + hz0) & HASH_MASK));
            float2 f001 = __ldg(tab + ((hx0 + hy0 + hz1) & HASH_MASK));
            float2 f010 = __ldg(tab + ((hx0 + hy1 + hz0) & HASH_MASK));
            float2 f011 = __ldg(tab + ((hx0 + hy1 + hz1) & HASH_MASK));
            float2 f100 = __ldg(tab + ((hx1 + hy0 + hz0) & HASH_MASK));
            float2 f101 = __ldg(tab + ((hx1 + hy0 + hz1) & HASH_MASK));
            float2 f110 = __ldg(tab + ((hx1 + hy1 + hz0) & HASH_MASK));
            float2 f111 = __ldg(tab + ((hx1 + hy1 + hz1) & HASH_MASK));
            acc0 = wx0 * (wy0 * (wz0 * f000.x + wz1 * f001.x) +
                          wy1 * (wz0 * f010.x + wz1 * f011.x)) +
                   wx1 * (wy0 * (wz0 * f100.x + wz1 * f101.x) +
                          wy1 * (wz0 * f110.x + wz1 * f111.x));
            acc1 = wx0 * (wy0 * (wz0 * f000.y + wz1 * f001.y) +
                          wy1 * (wz0 * f010.y + wz1 * f011.y)) +
                   wx1 * (wy0 * (wz0 * f100.y + wz1 * f101.y) +
                          wy1 * (wz0 * f110.y + wz1 * f111.y));
        }
    }

    outs[l][level] = make_float2(acc0, acc1);
    __syncthreads();

    // coalesced output: 512 threads write 32 points x 16 levels
    int i = tid >> 4, j = tid & 15;
    int on = n0 + i;
    if (on < n_points) {
        reinterpret_cast<float2*>(out)[(size_t)on * N_LEVELS + j] = outs[i][j];
    }
    (void)n;
}

extern "C" void kernel_launch(void* const* d_in, const int* in_sizes, int n_in,
                              void* d_out, int out_size)
{
    const float* x      = (const float*)d_in[0];
    const float* tables = (const float*)d_in[1];
    float*       out    = (float*)d_out;

    int n_points = in_sizes[0] / 3;

    Params p;
    for (int i = 0; i < N_LEVELS; i++) {
        double r = 16.0 * pow(32.0, (double)i / 15.0);   // host libm pow
        p.res[i] = (int)r;
    }

    // Dense quad levels 0..8
    int off = 0;
    p.dq_prefix[0] = 0;
    for (int i = 0; i < N_DQ; i++) {
        p.kind[i] = 0;
        p.base[i] = off;
        p.dA[i] = 0; p.dB[i] = 0;
        int cnt = p.res[i] * p.res[i] * p.res[i];
        off += cnt;
        p.dq_prefix[i + 1] = p.dq_prefix[i] + cnt;
    }

    int n_zp = 0, n_q2 = 0;
    for (int lvl = N_DQ; lvl < N_LEVELS; lvl++) {
        int r = p.res[lvl];
        if ((r & (r - 1)) == 0) {
            unsigned step = 131072u / (unsigned)r;
            p.kind[lvl] = 2;
            p.base[lvl] = n_q2 << HASH_BITS;
            p.dA[lvl] = PRIME3 * step;
            p.dB[lvl] = PRIME2 * step;
            p.q2_levels[n_q2++] = lvl;
        } else {
            unsigned d = 131072u / (unsigned)r;
            p.kind[lvl] = 1;
            p.base[lvl] = (n_zp * 2) << HASH_BITS;
            p.dA[lvl] = PRIME3 * d;
            p.dB[lvl] = PRIME3 * (d + 1);
            p.zp_levels[n_zp++] = lvl;
        }
    }

    int threads = 256;

    int total_dq = p.dq_prefix[N_DQ];
    fill_dq_kernel<<<(total_dq + threads - 1) / threads, threads>>>(
        tables, p, total_dq);

    if (n_zp > 0) {
        int total_zp = (n_zp * 2) << HASH_BITS;
        fill_zp2_kernel<<<(total_zp + threads - 1) / threads, threads>>>(
            tables, p, total_zp);
    }
    if (n_q2 > 0) {
        int total_q2 = n_q2 << HASH_BITS;
        fill_q2_kernel<<<(total_q2 + threads - 1) / threads, threads>>>(
            tables, p, total_q2);
    }

    int blocks = (n_points + 31) / 32;
    hash_encoding_kernel<<<blocks, 512>>>(x, tables, out, p, n_points);
}